// round 4
// baseline (speedup 1.0000x reference)
#include <cuda_runtime.h>

#define DIM     4096
#define HALF    2048
#define NLAYERS 12

// Precomputed cos/sin tables (written by sincos_kernel each launch — deterministic).
__device__ float g_cos[NLAYERS * HALF];
__device__ float g_sin[NLAYERS * HALF];

__global__ void sincos_kernel(const float* __restrict__ angles) {
    int i = blockIdx.x * blockDim.x + threadIdx.x;
    if (i < NLAYERS * HALF) {
        float s, c;
        sincosf(angles[i], &s, &c);
        g_cos[i] = c;
        g_sin[i] = s;
    }
}

// Bank-conflict-killing swizzle: XOR bits [5:8] of the word index into bits [2:4].
// Bijective on [0,4096); preserves 16B (float4) blocks since only bits >=2 change.
__device__ __forceinline__ int SW(int e) {
    return e ^ ((e >> 3) & 28) ^ ((e >> 4) & 16);
}

// 3 butterfly layers on 8 register-resident elements (local strides 1,2,4).
__device__ __forceinline__ void bf3(float x[8], const float (&c)[3][4], const float (&s)[3][4]) {
#pragma unroll
    for (int lz = 0; lz < 3; lz++) {
        const int sig = 1 << lz;
#pragma unroll
        for (int k = 0; k < 4; k++) {
            const int a = ((k >> lz) << (lz + 1)) | (k & (sig - 1));
            const int b = a + sig;
            float xl = x[a], xr = x[b];
            float t1 = xr * s[lz][k];
            float t2 = xl * s[lz][k];
            x[a] = fmaf(xl, c[lz][k], t1);
            x[b] = fmaf(xr, c[lz][k], -t2);
        }
    }
}

__global__ __launch_bounds__(512, 1)
void butterfly_kernel(const float* __restrict__ X, float* __restrict__ Y, int batch) {
    __shared__ float sb0[DIM];
    __shared__ float sb1[DIM];
    const int t = threadIdx.x;

    // ---------------- one-time per-CTA setup (amortized over ~54 rows) ----------------
    // c/s values this thread needs, cached in registers: 4 phases x 3 layers x 4 pairs.
    float cc[4][3][4], ss[4][3][4];
#pragma unroll
    for (int ph = 0; ph < 4; ph++) {
#pragma unroll
        for (int lz = 0; lz < 3; lz++) {
#pragma unroll
            for (int k = 0; k < 4; k++) {
                const int sig = 1 << lz;
                const int j = ((k >> lz) << (lz + 1)) | (k & (sig - 1)); // local left reg
                int e;                                                   // global element idx of left
                if      (ph == 0) e = 8 * t + j;
                else if (ph == 1) e = 64 * (t >> 3) + 8 * j + (t & 7);
                else if (ph == 2) e = 512 * (t >> 6) + 64 * j + (t & 63);
                else              e = 512 * j + t;
                const int l = ph * 3 + lz;
                const int p = ((e >> (l + 1)) << l) | (e & ((1 << l) - 1)); // pair index
                cc[ph][lz][k] = g_cos[l * HALF + p];
                ss[ph][lz][k] = g_sin[l * HALF + p];
            }
        }
    }

    // Per-thread invariant swizzled smem word addresses.
    const int st0a = SW(8 * t);       // phase-0 store, first float4
    const int st0b = SW(8 * t + 4);   // phase-0 store, second float4
    int a1[8], a2[8], a3[8];
#pragma unroll
    for (int j = 0; j < 8; j++) {
        a1[j] = SW(64 * (t >> 3) + 8 * j + (t & 7));     // phase-1 mapping (stride 8)
        a2[j] = SW(512 * (t >> 6) + 64 * j + (t & 63));  // phase-2 mapping (stride 64)
        a3[j] = SW(512 * j + t);                         // phase-3 mapping (stride 512)
    }

    // ---------------- persistent row loop ----------------
    float x[8];
    int row = blockIdx.x;
    if (row < batch) {
        const float4* p0 = reinterpret_cast<const float4*>(X + (size_t)row * DIM + 8 * t);
        float4 v0 = p0[0], v1 = p0[1];
        x[0] = v0.x; x[1] = v0.y; x[2] = v0.z; x[3] = v0.w;
        x[4] = v1.x; x[5] = v1.y; x[6] = v1.z; x[7] = v1.w;
    }

    for (; row < batch; row += gridDim.x) {
        // phase 0: layers 0..2 (strides 1,2,4) on contiguous 8 elements
        bf3(x, cc[0], ss[0]);

        // exchange 1: write contiguous, read stride-8 groups
        *reinterpret_cast<float4*>(&sb0[st0a]) = make_float4(x[0], x[1], x[2], x[3]);
        *reinterpret_cast<float4*>(&sb0[st0b]) = make_float4(x[4], x[5], x[6], x[7]);

        // prefetch next row while the smem pipeline runs
        float nx[8];
        const int nrow = row + gridDim.x;
        if (nrow < batch) {
            const float4* pn = reinterpret_cast<const float4*>(X + (size_t)nrow * DIM + 8 * t);
            float4 v0 = pn[0], v1 = pn[1];
            nx[0] = v0.x; nx[1] = v0.y; nx[2] = v0.z; nx[3] = v0.w;
            nx[4] = v1.x; nx[5] = v1.y; nx[6] = v1.z; nx[7] = v1.w;
        } else {
#pragma unroll
            for (int j = 0; j < 8; j++) nx[j] = 0.0f;
        }

        __syncthreads();
#pragma unroll
        for (int j = 0; j < 8; j++) x[j] = sb0[a1[j]];

        // phase 1: layers 3..5 (strides 8,16,32)
        bf3(x, cc[1], ss[1]);

#pragma unroll
        for (int j = 0; j < 8; j++) sb1[a1[j]] = x[j];
        __syncthreads();
#pragma unroll
        for (int j = 0; j < 8; j++) x[j] = sb1[a2[j]];

        // phase 2: layers 6..8 (strides 64,128,256)
        bf3(x, cc[2], ss[2]);

#pragma unroll
        for (int j = 0; j < 8; j++) sb0[a2[j]] = x[j];
        __syncthreads();
#pragma unroll
        for (int j = 0; j < 8; j++) x[j] = sb0[a3[j]];

        // phase 3: layers 9..11 (strides 512,1024,2048)
        bf3(x, cc[3], ss[3]);

        // store: element 512*j + t  -> fully coalesced 128B per warp per j
        float* yr = Y + (size_t)row * DIM + t;
#pragma unroll
        for (int j = 0; j < 8; j++) yr[512 * j] = x[j];

        __syncthreads();  // protect sb0 (phase-3 reads) from next row's phase-0 stores
#pragma unroll
        for (int j = 0; j < 8; j++) x[j] = nx[j];
    }
}

extern "C" void kernel_launch(void* const* d_in, const int* in_sizes, int n_in,
                              void* d_out, int out_size) {
    const float* x      = (const float*)d_in[0];
    const float* angles = (const float*)d_in[1];
    // d_in[2]/d_in[3] (left_idx/right_idx) are deterministic -> recomputed analytically.
    float* y = (float*)d_out;

    const int batch = in_sizes[0] / DIM;

    int nsm = 148;
    cudaDeviceGetAttribute(&nsm, cudaDevAttrMultiProcessorCount, 0);

    sincos_kernel<<<(NLAYERS * HALF + 511) / 512, 512>>>(angles);
    butterfly_kernel<<<nsm, 512>>>(x, y, batch);
}

// round 5
// speedup vs baseline: 1.2951x; 1.2951x over previous
#include <cuda_runtime.h>

#define DIM     4096
#define HALF    2048
#define NLAYERS 12

// Per-pair rotation constants: th = tan(theta/2), s = sin(theta).
// Rotation [[c,s],[-s,c]] applied as 3 shears (3 FMAs):
//   xa += th*xb;  xb -= s*xa;  xa += th*xb;
__device__ float g_th[NLAYERS * HALF];
__device__ float g_s [NLAYERS * HALF];

__global__ void prep_kernel(const float* __restrict__ angles) {
    int i = blockIdx.x * blockDim.x + threadIdx.x;
    if (i < NLAYERS * HALF) {
        float s, c;
        sincosf(angles[i], &s, &c);
        g_s[i]  = s;
        g_th[i] = s / (1.0f + c);
    }
}

// Bank-conflict-killing swizzle: XOR word-index bits [5:8] into bits [2:4].
// Bijective on [0,4096); preserves 16B blocks (only bits >=2 change).
__device__ __forceinline__ int SW(int e) {
    return e ^ ((e >> 3) & 28) ^ ((e >> 4) & 16);
}

// 3 butterfly layers on 8 register-resident elements (local strides 1,2,4),
// 3 FMAs per pair via tan-half-angle lifting.
__device__ __forceinline__ void bf3(float x[8], const float (&th)[3][4], const float (&sn)[3][4]) {
#pragma unroll
    for (int lz = 0; lz < 3; lz++) {
        const int sig = 1 << lz;
#pragma unroll
        for (int k = 0; k < 4; k++) {
            const int a = ((k >> lz) << (lz + 1)) | (k & (sig - 1));
            const int b = a + sig;
            x[a] = fmaf( th[lz][k], x[b], x[a]);
            x[b] = fmaf(-sn[lz][k], x[a], x[b]);
            x[a] = fmaf( th[lz][k], x[b], x[a]);
        }
    }
}

__global__ __launch_bounds__(512, 1)
void butterfly_kernel(const float* __restrict__ X, float* __restrict__ Y, int batch) {
    // 3 buffers, round-robin per phase -> only 3 syncthreads per row.
    __shared__ float sb[3][DIM];   // 48 KB exactly
    const int t = threadIdx.x;

    // ------- one-time per-CTA setup (amortized over ~54 rows) -------
    // Per-thread rotation constants in registers: 4 phases x 3 layers x 4 pairs.
    float tt[4][3][4], sn[4][3][4];
#pragma unroll
    for (int ph = 0; ph < 4; ph++) {
#pragma unroll
        for (int lz = 0; lz < 3; lz++) {
#pragma unroll
            for (int k = 0; k < 4; k++) {
                const int sig = 1 << lz;
                const int j = ((k >> lz) << (lz + 1)) | (k & (sig - 1)); // local left reg
                int e;                                                   // global elem idx of left
                if      (ph == 0) e = 8 * t + j;
                else if (ph == 1) e = 64 * (t >> 3) + 8 * j + (t & 7);
                else if (ph == 2) e = 512 * (t >> 6) + 64 * j + (t & 63);
                else              e = 512 * j + t;
                const int l = ph * 3 + lz;
                const int p = ((e >> (l + 1)) << l) | (e & ((1 << l) - 1)); // pair index
                tt[ph][lz][k] = g_th[l * HALF + p];
                sn[ph][lz][k] = g_s [l * HALF + p];
            }
        }
    }

    // Loop-invariant address bases (addresses themselves recomputed per use —
    // keeps live registers under the 128 cap, no spills).
    const int b1 = 64 * (t >> 3) + (t & 7);    // phase-1 mapping base (stride 8)
    const int b2 = 512 * (t >> 6) + (t & 63);  // phase-2 mapping base (stride 64)
    const int st0a = SW(8 * t);                // phase-0 store (float4-aligned)
    const int st0b = SW(8 * t + 4);

    // ------- persistent row loop -------
    float x[8];
    int row = blockIdx.x;
    if (row < batch) {
        const float4* p0 = reinterpret_cast<const float4*>(X + (size_t)row * DIM + 8 * t);
        float4 v0 = p0[0], v1 = p0[1];
        x[0] = v0.x; x[1] = v0.y; x[2] = v0.z; x[3] = v0.w;
        x[4] = v1.x; x[5] = v1.y; x[6] = v1.z; x[7] = v1.w;
    }

    for (; row < batch; row += gridDim.x) {
        // phase 0: layers 0..2 (strides 1,2,4) on contiguous 8 elements
        bf3(x, tt[0], sn[0]);

        *reinterpret_cast<float4*>(&sb[0][st0a]) = make_float4(x[0], x[1], x[2], x[3]);
        *reinterpret_cast<float4*>(&sb[0][st0b]) = make_float4(x[4], x[5], x[6], x[7]);

        // prefetch next row while the smem pipeline runs
        float nx[8];
        const int nrow = row + gridDim.x;
        if (nrow < batch) {
            const float4* pn = reinterpret_cast<const float4*>(X + (size_t)nrow * DIM + 8 * t);
            float4 v0 = pn[0], v1 = pn[1];
            nx[0] = v0.x; nx[1] = v0.y; nx[2] = v0.z; nx[3] = v0.w;
            nx[4] = v1.x; nx[5] = v1.y; nx[6] = v1.z; nx[7] = v1.w;
        } else {
#pragma unroll
            for (int j = 0; j < 8; j++) nx[j] = 0.0f;
        }

        __syncthreads();
#pragma unroll
        for (int j = 0; j < 8; j++) x[j] = sb[0][SW(b1 + 8 * j)];

        // phase 1: layers 3..5 (strides 8,16,32)
        bf3(x, tt[1], sn[1]);

#pragma unroll
        for (int j = 0; j < 8; j++) sb[1][SW(b1 + 8 * j)] = x[j];
        __syncthreads();
#pragma unroll
        for (int j = 0; j < 8; j++) x[j] = sb[1][SW(b2 + 64 * j)];

        // phase 2: layers 6..8 (strides 64,128,256)
        bf3(x, tt[2], sn[2]);

#pragma unroll
        for (int j = 0; j < 8; j++) sb[2][SW(b2 + 64 * j)] = x[j];
        __syncthreads();
#pragma unroll
        for (int j = 0; j < 8; j++) x[j] = sb[2][SW(512 * j + t)];

        // phase 3: layers 9..11 (strides 512,1024,2048)
        bf3(x, tt[3], sn[3]);

        // store: element 512*j + t -> fully coalesced 128B per warp per j
        float* yr = Y + (size_t)row * DIM + t;
#pragma unroll
        for (int j = 0; j < 8; j++) yr[512 * j] = x[j];

        // NO trailing sync: next row's first write hits sb[0], whose last read
        // (this row, phase-1 gather) is already dominated by this row's 2nd and
        // 3rd barriers for every thread.
#pragma unroll
        for (int j = 0; j < 8; j++) x[j] = nx[j];
    }
}

extern "C" void kernel_launch(void* const* d_in, const int* in_sizes, int n_in,
                              void* d_out, int out_size) {
    const float* x      = (const float*)d_in[0];
    const float* angles = (const float*)d_in[1];
    // d_in[2]/d_in[3] (left_idx/right_idx) are deterministic -> recomputed analytically.
    float* y = (float*)d_out;

    const int batch = in_sizes[0] / DIM;

    int nsm = 148;
    cudaDeviceGetAttribute(&nsm, cudaDevAttrMultiProcessorCount, 0);

    prep_kernel<<<(NLAYERS * HALF + 511) / 512, 512>>>(angles);
    butterfly_kernel<<<nsm, 512>>>(x, y, batch);
}